// round 10
// baseline (speedup 1.0000x reference)
#include <cuda_runtime.h>
#include <math.h>

#define Hd 512
#define Wd 512
#define NPTS 2048           // 64 segments * 32 samples
#define NT 512
#define RADIUS 12.0f        // sigma(-12) = 6.1e-6 truncation
#define NBIN 16             // 32-pixel bins, one per warp
#define CAP 128             // per-bin capacity

// Per-edge invariants, computed once: (x0, y0, dx, inv_dy). Masked: y0 = NaN.
__device__ float4 g_edge[NPTS];

__shared__ float2 s_bin[NBIN][CAP];   // 16 KB: (xc, w) per bin
__shared__ int    s_cnt[NBIN];
__shared__ float  s_wc[NBIN + 1];     // full-weight buckets: wc[b] -> warps < b
__shared__ float  s_wcs[NBIN];        // suffix sums: wcs[j] = sum_{b>j} wc[b]

__device__ __forceinline__ float fsig(float z) {
    return __fdividef(1.0f, 1.0f + __expf(-z));
}

__device__ __forceinline__ float2 bez(const float2* c2, int idx) {
    int seg = idx >> 5;
    int k   = idx & 31;
    float t  = (float)k * (1.0f / 31.0f);
    float mt = 1.0f - t;
    float2 p0 = c2[3 * seg + 0];
    float2 p1 = c2[3 * seg + 1];
    float2 p2 = c2[3 * seg + 2];
    float2 p3 = c2[3 * seg + 3];
    float w0 = mt * mt * mt;
    float w1 = 3.0f * mt * mt * t;
    float w2 = 3.0f * mt * t * t;
    float w3 = t * t * t;
    return make_float2(w0 * p0.x + w1 * p1.x + w2 * p2.x + w3 * p3.x,
                       w0 * p0.y + w1 * p1.y + w2 * p2.y + w3 * p3.y);
}

// ---- Kernel 1: per-edge invariants; no smem, no sync, no atomics ----
__global__ __launch_bounds__(NT)
void build_edges(const float* __restrict__ cp) {
    const int e = blockIdx.x * NT + threadIdx.x;        // 0..2047
    const float2* c2 = (const float2*)cp;
    float2 a = bez(c2, e);
    float2 b = bez(c2, (e + 1) & (NPTS - 1));
    float dy = b.y - a.y;
    float y0 = a.y;
    float dyp = dy + 1e-8f;
    float invdy = 1.0f / dyp;
    if (fabsf(dy) < 1e-6f) {                            // reference mask==0
        y0 = __int_as_float(0x7fffffff);                // NaN -> band test rejects
        invdy = 1.0f;
    }
    g_edge[e] = make_float4(a.x, y0, b.x - a.x, invdy);
}

// ---- Kernel 2: one block per row; warp w owns pixels [32w, 32w+31] ----
__global__ __launch_bounds__(NT)
void render_row(const float* __restrict__ color, float* __restrict__ out) {
    const int tid  = threadIdx.x;
    const int lane = tid & 31;
    const int wp   = tid >> 5;
    const int y    = blockIdx.x;
    const float gy = (float)y;

    if (tid < NBIN) { s_cnt[tid] = 0; s_wc[tid] = 0.0f; }
    if (tid == 0) s_wc[NBIN] = 0.0f;
    __syncthreads();

    // --- Phase A: 4 coalesced edge loads per thread ---
    #pragma unroll
    for (int j = 0; j < 4; ++j) {
        float4 E = g_edge[tid + j * NT];                // (x0, y0, dx, inv_dy)
        float t = (gy - E.y) * E.w;
        if (!(t >= -1.0f && t <= 2.0f)) continue;       // NaN-rejecting band
        // sig(20t)*sig(20-20t) with a single reciprocal
        float w = __fdividef(1.0f,
                 (1.0f + __expf(-20.0f * t)) * (1.0f + __expf(20.0f * t - 20.0f)));
        w = copysignf(w, E.w);                          // sign(dy)
        float xc = fmaf(t, E.z, E.x);

        int b0r = (int)floorf((xc - RADIUS) * (1.0f / 32.0f));
        int b1r = (int)floorf((xc + RADIUS) * (1.0f / 32.0f));
        if (b1r < 0) continue;                          // fully left: zero
        if (b0r >= NBIN) {                              // fully right: all full
            atomicAdd(&s_wc[NBIN], w);
            continue;
        }
        if (b0r > 0) atomicAdd(&s_wc[b0r], w);          // warps < b0r get w
        int b0 = max(b0r, 0);
        int b1 = min(b1r, NBIN - 1);
        for (int bb = b0; bb <= b1; ++bb) {
            int q = atomicAdd(&s_cnt[bb], 1);
            if (q < CAP) s_bin[bb][q] = make_float2(xc, w);
        }
    }
    __syncthreads();

    // --- warp 0: suffix-scan the 16 buckets while others start Phase B ---
    if (wp == 0 && lane < NBIN) {
        float v = s_wc[lane + 1];
        #pragma unroll
        for (int o = 1; o < NBIN; o <<= 1) {
            float nb = __shfl_down_sync(0x0000ffffu, v, o);
            if (lane + o < NBIN) v += nb;
        }
        s_wcs[lane] = v;            // wcs[j] = sum_{b > j} wc[b]
    }

    // --- Phase B: thread owns pixel x=tid; warp scans exactly its own bin ---
    float wind = 0.0f;
    {
        const float fx = (float)tid;
        int m = min(s_cnt[wp], CAP);
        for (int i = 0; i < m; ++i) {
            float2 E = s_bin[wp][i];                    // broadcast LDS
            float z = E.x - fx;
            if (z > RADIUS)        wind += E.y;         // full weight
            else if (z >= -RADIUS) wind += E.y * fsig(z);
        }
    }
    __syncthreads();

    // --- combine + output ---
    wind += s_wcs[wp];
    float alpha = fsig(4.0f * wind);
    float cr = __ldg(&color[0]), cg = __ldg(&color[1]), cb = __ldg(&color[2]);
    ((float4*)out)[y * Wd + tid] = make_float4(cr, cg, cb, alpha);
}

extern "C" void kernel_launch(void* const* d_in, const int* in_sizes, int n_in,
                              void* d_out, int out_size) {
    (void)in_sizes; (void)n_in; (void)out_size;
    const float* cp    = (const float*)d_in[0];   // (193,2) float32
    const float* color = (const float*)d_in[1];   // (3,)    float32
    float* out = (float*)d_out;                   // (512,512,4) float32
    build_edges<<<NPTS / NT, NT>>>(cp);           // 4 blocks, no atomics
    render_row<<<Hd, NT>>>(color, out);
}